// round 2
// baseline (speedup 1.0000x reference)
#include <cuda_runtime.h>
#include <cuda_bf16.h>

#define SDIM 2048
#define BDIM 4
#define HDIM 1024
#define MPROJ (SDIM * BDIM)   // 8192

// Scratch (device globals: allocation-free, graph-capturable)
__device__ float g_Q[(size_t)BDIM * SDIM * HDIM];   // 32 MB  [B][S][H]
__device__ float g_K[(size_t)BDIM * SDIM * HDIM];   // 32 MB  [B][S][H]
__device__ float g_V[(size_t)BDIM * SDIM * HDIM];   // 32 MB  [B][S][H]
__device__ float g_SC[(size_t)BDIM * SDIM * SDIM];  // 64 MB  [B][S][S]

// Packed f32x2 FMA: d = a * b + d (elementwise on both 32-bit halves).
// ptxas will NOT auto-fuse this from C++ — must be explicit PTX (sm_100+).
__device__ __forceinline__ void ffma2(unsigned long long& d,
                                      unsigned long long a,
                                      unsigned long long b)
{
    asm("fma.rn.f32x2 %0, %1, %2, %0;" : "+l"(d) : "l"(a), "l"(b));
}

__device__ __forceinline__ float2 unpack2(unsigned long long v)
{
    float2 f;
    asm("mov.b64 {%0, %1}, %2;" : "=f"(f.x), "=f"(f.y) : "l"(v));
    return f;
}

// ---------------------------------------------------------------------------
// GEMM skeleton: 128x128 tile, BK=8, 256 threads, 8x8 accum per thread,
// inner product via packed fma.rn.f32x2.
// A tile stored DUPLICATED in smem: As2[k][2*row] = As2[k][2*row+1] = a, so a
// single LDS.128 yields (a_i, a_i, a_{i+1}, a_{i+1}) — lane-dup packing free.
// ---------------------------------------------------------------------------

#define GEMM_CORE_DECLS                                                        \
    __shared__ float As2[8][264 + 8];  /* duplicated A: 256 cols used */       \
    __shared__ float Bs[8][132];                                               \
    const int t    = threadIdx.x;                                              \
    const int lrow = t >> 1;                                                   \
    const int lk4  = (t & 1) * 4;                                              \
    const int ty   = t >> 4;                                                   \
    const int tx   = t & 15;                                                   \
    unsigned long long c2[8][4];                                               \
    _Pragma("unroll")                                                          \
    for (int i = 0; i < 8; i++)                                                \
        _Pragma("unroll")                                                      \
        for (int j = 0; j < 4; j++) c2[i][j] = 0ULL;

#define GEMM_INNER_8KK                                                         \
    _Pragma("unroll")                                                          \
    for (int kk = 0; kk < 8; kk++) {                                           \
        ulonglong2 a01, a23, a45, a67, b03, b47;                               \
        {                                                                      \
            const ulonglong2* ap = (const ulonglong2*)&As2[kk][ty * 16];       \
            a01 = ap[0]; a23 = ap[1]; a45 = ap[2]; a67 = ap[3];                \
            const ulonglong2* bp = (const ulonglong2*)&Bs[kk][tx * 8];         \
            b03 = bp[0]; b47 = bp[1];                                          \
        }                                                                      \
        ffma2(c2[0][0], a01.x, b03.x); ffma2(c2[0][1], a01.x, b03.y);          \
        ffma2(c2[0][2], a01.x, b47.x); ffma2(c2[0][3], a01.x, b47.y);          \
        ffma2(c2[1][0], a01.y, b03.x); ffma2(c2[1][1], a01.y, b03.y);          \
        ffma2(c2[1][2], a01.y, b47.x); ffma2(c2[1][3], a01.y, b47.y);          \
        ffma2(c2[2][0], a23.x, b03.x); ffma2(c2[2][1], a23.x, b03.y);          \
        ffma2(c2[2][2], a23.x, b47.x); ffma2(c2[2][3], a23.x, b47.y);          \
        ffma2(c2[3][0], a23.y, b03.x); ffma2(c2[3][1], a23.y, b03.y);          \
        ffma2(c2[3][2], a23.y, b47.x); ffma2(c2[3][3], a23.y, b47.y);          \
        ffma2(c2[4][0], a45.x, b03.x); ffma2(c2[4][1], a45.x, b03.y);          \
        ffma2(c2[4][2], a45.x, b47.x); ffma2(c2[4][3], a45.x, b47.y);          \
        ffma2(c2[5][0], a45.y, b03.x); ffma2(c2[5][1], a45.y, b03.y);          \
        ffma2(c2[5][2], a45.y, b47.x); ffma2(c2[5][3], a45.y, b47.y);          \
        ffma2(c2[6][0], a67.x, b03.x); ffma2(c2[6][1], a67.x, b03.y);          \
        ffma2(c2[6][2], a67.x, b47.x); ffma2(c2[6][3], a67.x, b47.y);          \
        ffma2(c2[7][0], a67.y, b03.x); ffma2(c2[7][1], a67.y, b03.y);          \
        ffma2(c2[7][2], a67.y, b47.x); ffma2(c2[7][3], a67.y, b47.y);          \
    }

// Store one A element duplicated (STS.64) + one B element.
#define STORE_TILE_NT(av_, bw_)                                                \
    *(float2*)&As2[lk4 + 0][2 * lrow] = make_float2((av_).x, (av_).x);         \
    *(float2*)&As2[lk4 + 1][2 * lrow] = make_float2((av_).y, (av_).y);         \
    *(float2*)&As2[lk4 + 2][2 * lrow] = make_float2((av_).z, (av_).z);         \
    *(float2*)&As2[lk4 + 3][2 * lrow] = make_float2((av_).w, (av_).w);         \
    Bs[lk4 + 0][lrow] = (bw_).x; Bs[lk4 + 1][lrow] = (bw_).y;                  \
    Bs[lk4 + 2][lrow] = (bw_).z; Bs[lk4 + 3][lrow] = (bw_).w;

// Q/K/V projection: C[m][n] = sum_h x[m][h] * W[n][h] + bias[n]
// x is [S,B,H] flattened to [M=8192][K=1024] with m = s*B + b.
// Output scattered to [B][S][H].
__global__ void __launch_bounds__(256) proj_kernel(
    const float* __restrict__ x,
    const float* __restrict__ Wq, const float* __restrict__ bq,
    const float* __restrict__ Wk, const float* __restrict__ bk,
    const float* __restrict__ Wv, const float* __restrict__ bv)
{
    const float* W; const float* bias; float* out;
    if (blockIdx.z == 0)      { W = Wq; bias = bq; out = g_Q; }
    else if (blockIdx.z == 1) { W = Wk; bias = bk; out = g_K; }
    else                      { W = Wv; bias = bv; out = g_V; }

    GEMM_CORE_DECLS
    const int m0 = blockIdx.y * 128;
    const int n0 = blockIdx.x * 128;

    const float* Ag = x + (size_t)(m0 + lrow) * HDIM + lk4;
    const float* Bg = W + (size_t)(n0 + lrow) * HDIM + lk4;

    float4 av = *(const float4*)Ag;
    float4 bw = *(const float4*)Bg;

    for (int k0 = 0; k0 < HDIM; k0 += 8) {
        __syncthreads();
        STORE_TILE_NT(av, bw)
        __syncthreads();
        if (k0 + 8 < HDIM) {
            av = *(const float4*)(Ag + k0 + 8);
            bw = *(const float4*)(Bg + k0 + 8);
        }
        GEMM_INNER_8KK
    }

#pragma unroll
    for (int i = 0; i < 8; i++) {
        int m = m0 + ty * 8 + i;
        int s = m >> 2;            // m = s*B + b, B=4
        int b = m & 3;
        float* orow = out + ((size_t)b * SDIM + s) * HDIM + n0 + tx * 8;
#pragma unroll
        for (int j = 0; j < 4; j++) {
            float2 v = unpack2(c2[i][j]);
            orow[2 * j + 0] = v.x + bias[n0 + tx * 8 + 2 * j + 0];
            orow[2 * j + 1] = v.y + bias[n0 + tx * 8 + 2 * j + 1];
        }
    }
}

// scores[b][q][k] = (Q[b][q] . K[b][k]) / 32 + beta * ssm[b][q][k]
__global__ void __launch_bounds__(256) scores_kernel(
    const float* __restrict__ ssm, const float* __restrict__ beta_p)
{
    const int bz = blockIdx.z;
    const float* A = g_Q + (size_t)bz * SDIM * HDIM;
    const float* B = g_K + (size_t)bz * SDIM * HDIM;

    GEMM_CORE_DECLS
    const int m0 = blockIdx.y * 128;
    const int n0 = blockIdx.x * 128;

    const float* Ag = A + (size_t)(m0 + lrow) * HDIM + lk4;
    const float* Bg = B + (size_t)(n0 + lrow) * HDIM + lk4;

    float4 av = *(const float4*)Ag;
    float4 bw = *(const float4*)Bg;

    for (int k0 = 0; k0 < HDIM; k0 += 8) {
        __syncthreads();
        STORE_TILE_NT(av, bw)
        __syncthreads();
        if (k0 + 8 < HDIM) {
            av = *(const float4*)(Ag + k0 + 8);
            bw = *(const float4*)(Bg + k0 + 8);
        }
        GEMM_INNER_8KK
    }

    const float beta = *beta_p;
    const float inv_scale = 1.0f / 32.0f;   // 1/sqrt(H)
#pragma unroll
    for (int i = 0; i < 8; i++) {
        int m = m0 + ty * 8 + i;
        const float* srow = ssm + ((size_t)bz * SDIM + m) * SDIM + n0 + tx * 8;
        float* drow = g_SC + ((size_t)bz * SDIM + m) * SDIM + n0 + tx * 8;
#pragma unroll
        for (int j = 0; j < 4; j++) {
            float2 v = unpack2(c2[i][j]);
            drow[2 * j + 0] = v.x * inv_scale + beta * srow[2 * j + 0];
            drow[2 * j + 1] = v.y * inv_scale + beta * srow[2 * j + 1];
        }
    }
}

// Row softmax over S=2048 elements, one CTA (256 threads) per row, in-place.
__global__ void __launch_bounds__(256) softmax_kernel()
{
    __shared__ float redm[8];
    __shared__ float reds[8];
    __shared__ float bcast[2];

    const int row = blockIdx.x;                 // b*S + q
    float* p = g_SC + (size_t)row * SDIM;
    const int t = threadIdx.x;
    const int lane = t & 31, warp = t >> 5;

    float v[8];
    float m = -3.0e38f;
#pragma unroll
    for (int i = 0; i < 8; i++) { v[i] = p[t + 256 * i]; m = fmaxf(m, v[i]); }
#pragma unroll
    for (int o = 16; o; o >>= 1) m = fmaxf(m, __shfl_xor_sync(0xffffffffu, m, o));
    if (lane == 0) redm[warp] = m;
    __syncthreads();
    if (t == 0) {
        float mm = redm[0];
#pragma unroll
        for (int w = 1; w < 8; w++) mm = fmaxf(mm, redm[w]);
        bcast[0] = mm;
    }
    __syncthreads();
    m = bcast[0];

    float ssum = 0.0f;
#pragma unroll
    for (int i = 0; i < 8; i++) { v[i] = __expf(v[i] - m); ssum += v[i]; }
#pragma unroll
    for (int o = 16; o; o >>= 1) ssum += __shfl_xor_sync(0xffffffffu, ssum, o);
    if (lane == 0) reds[warp] = ssum;
    __syncthreads();
    if (t == 0) {
        float s = reds[0];
#pragma unroll
        for (int w = 1; w < 8; w++) s += reds[w];
        bcast[1] = 1.0f / s;
    }
    __syncthreads();
    const float inv = bcast[1];
#pragma unroll
    for (int i = 0; i < 8; i++) p[t + 256 * i] = v[i] * inv;
}

// out[s=q][b][h] = sum_k attn[b][q][k] * V[b][k][h]     (GEMM-NN)
__global__ void __launch_bounds__(256) av_kernel(float* __restrict__ out)
{
    const int bz = blockIdx.z;
    const float* A  = g_SC + (size_t)bz * SDIM * SDIM;   // [M=S][K=S], K-contig
    const float* Bv = g_V  + (size_t)bz * SDIM * HDIM;   // [K=S][N=H], N-contig

    GEMM_CORE_DECLS
    const int m0 = blockIdx.y * 128;
    const int n0 = blockIdx.x * 128;
    const int kr = t >> 5;              // B: k row, 0..7
    const int c4 = (t & 31) * 4;        // B: n offset

    const float* Ag = A  + (size_t)(m0 + lrow) * SDIM + lk4;
    const float* Bg = Bv + (size_t)kr * HDIM + n0 + c4;

    float4 av = *(const float4*)Ag;
    float4 bw = *(const float4*)Bg;

    for (int k0 = 0; k0 < SDIM; k0 += 8) {
        __syncthreads();
        *(float2*)&As2[lk4 + 0][2 * lrow] = make_float2(av.x, av.x);
        *(float2*)&As2[lk4 + 1][2 * lrow] = make_float2(av.y, av.y);
        *(float2*)&As2[lk4 + 2][2 * lrow] = make_float2(av.z, av.z);
        *(float2*)&As2[lk4 + 3][2 * lrow] = make_float2(av.w, av.w);
        *(float4*)&Bs[kr][c4] = bw;
        __syncthreads();
        if (k0 + 8 < SDIM) {
            av = *(const float4*)(Ag + k0 + 8);
            bw = *(const float4*)(Bg + (size_t)(k0 + 8) * HDIM);
        }
        GEMM_INNER_8KK
    }

    // out is [S][B][H]: element (q=m, b=bz, h=n)
#pragma unroll
    for (int i = 0; i < 8; i++) {
        int m = m0 + ty * 8 + i;
        float* orow = out + ((size_t)m * BDIM + bz) * HDIM + n0 + tx * 8;
#pragma unroll
        for (int j = 0; j < 4; j++) {
            float2 v = unpack2(c2[i][j]);
            orow[2 * j + 0] = v.x;
            orow[2 * j + 1] = v.y;
        }
    }
}

extern "C" void kernel_launch(void* const* d_in, const int* in_sizes, int n_in,
                              void* d_out, int out_size)
{
    const float* x    = (const float*)d_in[0];
    const float* ssm  = (const float*)d_in[1];
    const float* Wq   = (const float*)d_in[2];
    const float* bq   = (const float*)d_in[3];
    const float* Wk   = (const float*)d_in[4];
    const float* bk   = (const float*)d_in[5];
    const float* Wv   = (const float*)d_in[6];
    const float* bv   = (const float*)d_in[7];
    const float* beta = (const float*)d_in[8];
    float* out = (float*)d_out;

    dim3 blk(256);
    proj_kernel<<<dim3(HDIM / 128, MPROJ / 128, 3), blk>>>(x, Wq, bq, Wk, bk, Wv, bv);
    scores_kernel<<<dim3(SDIM / 128, SDIM / 128, BDIM), blk>>>(ssm, beta);
    softmax_kernel<<<dim3(BDIM * SDIM), blk>>>();
    av_kernel<<<dim3(HDIM / 128, SDIM / 128, BDIM), blk>>>(out);
}

// round 5
// speedup vs baseline: 5.2882x; 5.2882x over previous
#include <cuda_runtime.h>
#include <cuda_fp16.h>
#include <cstdint>

#define SDIM 2048
#define BDIM 4
#define HDIM 1024

// fp16 scratch (device globals: allocation-free, graph-capturable)
__device__ __half g_Qh[(size_t)BDIM * SDIM * HDIM];   // [b][s][h] 16 MB
__device__ __half g_Kh[(size_t)BDIM * SDIM * HDIM];   // [b][s][h] 16 MB
__device__ __half g_VT[(size_t)BDIM * HDIM * SDIM];   // [b][h][s] 16 MB
__device__ __half g_Sh[(size_t)BDIM * SDIM * SDIM];   // [b][q][k] 32 MB scores->attn

// ---------------------------------------------------------------------------
// helpers (base PTX only: family-portable on compute_103)
// ---------------------------------------------------------------------------
static __device__ __forceinline__ uint32_t su32(const void* p) {
    uint32_t a;
    asm("{ .reg .u64 t; cvta.to.shared.u64 t, %1; cvt.u32.u64 %0, t; }" : "=r"(a) : "l"(p));
    return a;
}
static __device__ __forceinline__ void cp16(uint32_t dst, const void* src) {
    asm volatile("cp.async.cg.shared.global [%0], [%1], 16;" :: "r"(dst), "l"(src));
}
static __device__ __forceinline__ void cp_commit() {
    asm volatile("cp.async.commit_group;" ::: "memory");
}
template <int N>
static __device__ __forceinline__ void cp_wait() {
    asm volatile("cp.async.wait_group %0;" :: "n"(N) : "memory");
}
static __device__ __forceinline__ void ldm_x4(uint32_t* r, uint32_t addr) {
    asm volatile("ldmatrix.sync.aligned.m8n8.x4.shared.b16 {%0,%1,%2,%3}, [%4];"
                 : "=r"(r[0]), "=r"(r[1]), "=r"(r[2]), "=r"(r[3]) : "r"(addr));
}
static __device__ __forceinline__ void mma16816(float* c, const uint32_t* a,
                                                uint32_t b0, uint32_t b1) {
    asm volatile(
        "mma.sync.aligned.m16n8k16.row.col.f32.f16.f16.f32 "
        "{%0,%1,%2,%3}, {%4,%5,%6,%7}, {%8,%9}, {%0,%1,%2,%3};"
        : "+f"(c[0]), "+f"(c[1]), "+f"(c[2]), "+f"(c[3])
        : "r"(a[0]), "r"(a[1]), "r"(a[2]), "r"(a[3]), "r"(b0), "r"(b1));
}
static __device__ __forceinline__ uint32_t h2bits(__half2 h) {
    return *reinterpret_cast<uint32_t*>(&h);
}

// ---------------------------------------------------------------------------
// Smem tile: 128 rows x 32 halves (64B), padded to 80B/row (conflict-free
// ldmatrix: 80B stride -> 8 rows hit 8 distinct 16B columns mod 128B).
// Stage layout: A @ +0 (10240B), B @ +10240. Stages at +0 / +20480.
// ---------------------------------------------------------------------------
#define ROWB  80
#define STAGE 20480
#define SMEMB (2 * STAGE)          // 40960

static __device__ __forceinline__ void compute_chunk(
    uint32_t sbase, int lane, int wm, int wn, float acc[2][8][4])
{
#pragma unroll
    for (int kk = 0; kk < 2; kk++) {
        uint32_t a[2][4];
#pragma unroll
        for (int mi = 0; mi < 2; mi++) {
            uint32_t addr = sbase
                + (uint32_t)(wm * 32 + mi * 16 + (lane & 15)) * ROWB
                + kk * 32 + ((lane >> 4) << 4);
            ldm_x4(a[mi], addr);
        }
        uint32_t b[4][4];
#pragma unroll
        for (int ni2 = 0; ni2 < 4; ni2++) {
            uint32_t addr = sbase + 10240u
                + (uint32_t)(wn * 64 + ni2 * 16 + (lane & 7) + ((lane >> 4) << 3)) * ROWB
                + kk * 32 + (((lane >> 3) & 1) << 4);
            ldm_x4(b[ni2], addr);
        }
#pragma unroll
        for (int mi = 0; mi < 2; mi++)
#pragma unroll
            for (int ni = 0; ni < 8; ni++)
                mma16816(acc[mi][ni], a[mi],
                         b[ni >> 1][(ni & 1) * 2], b[ni >> 1][(ni & 1) * 2 + 1]);
    }
}

static __device__ __forceinline__ void cpa_issue(
    uint32_t sm, const char* Ag, size_t ldA, const char* Bg, size_t ldB,
    size_t kbyte, int t)
{
    const int row = t >> 1;
    const int c = (t & 1) * 32;
    uint32_t da = sm + (uint32_t)row * ROWB + c;
    const char* sa = Ag + (size_t)row * ldA + kbyte + c;
    cp16(da, sa); cp16(da + 16, sa + 16);
    uint32_t db = sm + 10240u + (uint32_t)row * ROWB + c;
    const char* sb = Bg + (size_t)row * ldB + kbyte + c;
    cp16(db, sb); cp16(db + 16, sb + 16);
}

static __device__ __forceinline__ void hmma_nt(
    const char* Ag, size_t ldA, const char* Bg, size_t ldB, int nch,
    uint32_t sm0, int t, float acc[2][8][4])
{
    const int lane = t & 31, wm = (t >> 5) & 3, wn = t >> 7;
    cpa_issue(sm0, Ag, ldA, Bg, ldB, 0, t);
    cp_commit();
    cpa_issue(sm0 + STAGE, Ag, ldA, Bg, ldB, 64, t);
    cp_commit();
    for (int i = 0; i < nch; i++) {
        if (i + 1 < nch) cp_wait<1>(); else cp_wait<0>();
        __syncthreads();
        compute_chunk(sm0 + (i & 1) * STAGE, lane, wm, wn, acc);
        __syncthreads();
        if (i + 2 < nch) {
            cpa_issue(sm0 + (i & 1) * STAGE, Ag, ldA, Bg, ldB, (size_t)(i + 2) * 64, t);
            cp_commit();
        }
    }
}

#define ACC_INIT(acc)                                                          \
    _Pragma("unroll")                                                          \
    for (int i_ = 0; i_ < 2; i_++)                                             \
        _Pragma("unroll")                                                      \
        for (int j_ = 0; j_ < 8; j_++)                                         \
            _Pragma("unroll")                                                  \
            for (int k_ = 0; k_ < 4; k_++) (acc)[i_][j_][k_] = 0.0f;

// ---------------------------------------------------------------------------
// proj: C[m][n] = sum_h x[m][h]*W[n][h] + bias[n]; fp32 in, fp16 out.
// z=0 -> g_Qh, z=1 -> g_Kh, z=2 -> V transposed into g_VT[b][h][s].
// ---------------------------------------------------------------------------
__global__ void __launch_bounds__(256) proj_k(
    const float* __restrict__ x,
    const float* __restrict__ Wq, const float* __restrict__ bq,
    const float* __restrict__ Wk, const float* __restrict__ bk,
    const float* __restrict__ Wv, const float* __restrict__ bv)
{
    extern __shared__ char dsm[];
    const int t = threadIdx.x;
    const int lane = t & 31, wm = (t >> 5) & 3, wn = t >> 7;
    const uint32_t sm0 = su32(dsm);
    const int z = blockIdx.z;
    const float* W; const float* bias;
    if (z == 0)      { W = Wq; bias = bq; }
    else if (z == 1) { W = Wk; bias = bk; }
    else             { W = Wv; bias = bv; }
    const int m0 = blockIdx.y * 128, n0 = blockIdx.x * 128;
    const char* Ab = (const char*)(x + (size_t)m0 * HDIM);
    const char* Bb = (const char*)(W + (size_t)n0 * HDIM);

    float acc[2][8][4];
    ACC_INIT(acc)

    const int row = t >> 1;
    const int cf = (t & 1) * 64;       // byte offset of this thread's 16 floats
    const size_t ldf = HDIM * 4;
    char* const sAp = dsm + (size_t)row * ROWB + (t & 1) * 32;
    char* const sBp = dsm + 10240 + (size_t)row * ROWB + (t & 1) * 32;

    float4 ra[4], rb[4];
#pragma unroll
    for (int j = 0; j < 4; j++) {
        ra[j] = *(const float4*)(Ab + (size_t)row * ldf + cf + j * 16);
        rb[j] = *(const float4*)(Bb + (size_t)row * ldf + cf + j * 16);
    }
    for (int i = 0; i < HDIM / 32; i++) {
        __syncthreads();
        *(uint4*)sAp = make_uint4(
            h2bits(__floats2half2_rn(ra[0].x, ra[0].y)),
            h2bits(__floats2half2_rn(ra[0].z, ra[0].w)),
            h2bits(__floats2half2_rn(ra[1].x, ra[1].y)),
            h2bits(__floats2half2_rn(ra[1].z, ra[1].w)));
        *(uint4*)(sAp + 16) = make_uint4(
            h2bits(__floats2half2_rn(ra[2].x, ra[2].y)),
            h2bits(__floats2half2_rn(ra[2].z, ra[2].w)),
            h2bits(__floats2half2_rn(ra[3].x, ra[3].y)),
            h2bits(__floats2half2_rn(ra[3].z, ra[3].w)));
        *(uint4*)sBp = make_uint4(
            h2bits(__floats2half2_rn(rb[0].x, rb[0].y)),
            h2bits(__floats2half2_rn(rb[0].z, rb[0].w)),
            h2bits(__floats2half2_rn(rb[1].x, rb[1].y)),
            h2bits(__floats2half2_rn(rb[1].z, rb[1].w)));
        *(uint4*)(sBp + 16) = make_uint4(
            h2bits(__floats2half2_rn(rb[2].x, rb[2].y)),
            h2bits(__floats2half2_rn(rb[2].z, rb[2].w)),
            h2bits(__floats2half2_rn(rb[3].x, rb[3].y)),
            h2bits(__floats2half2_rn(rb[3].z, rb[3].w)));
        __syncthreads();
        if (i + 1 < HDIM / 32) {
            const size_t kb = (size_t)(i + 1) * 128;
#pragma unroll
            for (int j = 0; j < 4; j++) {
                ra[j] = *(const float4*)(Ab + (size_t)row * ldf + kb + cf + j * 16);
                rb[j] = *(const float4*)(Bb + (size_t)row * ldf + kb + cf + j * 16);
            }
        }
        compute_chunk(sm0, lane, wm, wn, acc);
    }

    const int g = lane >> 2, qd = lane & 3;
    if (z < 2) {
        __half* out = z ? g_Kh : g_Qh;
#pragma unroll
        for (int mi = 0; mi < 2; mi++)
#pragma unroll
            for (int h2 = 0; h2 < 2; h2++) {
                const int m = m0 + wm * 32 + mi * 16 + g + h2 * 8;
                const int s = m >> 2, b = m & 3;
                __half* orow = out + ((size_t)b * SDIM + s) * HDIM + n0;
#pragma unroll
                for (int ni = 0; ni < 8; ni++) {
                    const int col = wn * 64 + ni * 8 + qd * 2;
                    const float v0 = acc[mi][ni][h2 * 2 + 0] + bias[n0 + col];
                    const float v1 = acc[mi][ni][h2 * 2 + 1] + bias[n0 + col + 1];
                    *(__half2*)(orow + col) = __floats2half2_rn(v0, v1);
                }
            }
    } else {
        __syncthreads();
        __half* Tr = (__half*)dsm;     // 128 x 128, stride 132 halves (33.8KB<40.96KB)
#pragma unroll
        for (int mi = 0; mi < 2; mi++)
#pragma unroll
            for (int h2 = 0; h2 < 2; h2++) {
                const int ml = wm * 32 + mi * 16 + g + h2 * 8;
#pragma unroll
                for (int ni = 0; ni < 8; ni++) {
                    const int col = wn * 64 + ni * 8 + qd * 2;
                    const float v0 = acc[mi][ni][h2 * 2 + 0] + bias[n0 + col];
                    const float v1 = acc[mi][ni][h2 * 2 + 1] + bias[n0 + col + 1];
                    *(__half2*)(Tr + (size_t)ml * 132 + col) = __floats2half2_rn(v0, v1);
                }
            }
        __syncthreads();
        const int s0 = blockIdx.y * 32;
#pragma unroll 1
        for (int rr = t; rr < 512; rr += 256) {
            const int h = rr >> 2, b = rr & 3;
            __half* dst = g_VT + ((size_t)b * HDIM + n0 + h) * SDIM + s0;
            uint32_t u[16];
#pragma unroll
            for (int s = 0; s < 32; s += 2) {
                u[s >> 1] = h2bits(__halves2half2(
                    Tr[(size_t)(s * 4 + b) * 132 + h],
                    Tr[(size_t)((s + 1) * 4 + b) * 132 + h]));
            }
#pragma unroll
            for (int j = 0; j < 4; j++)
                *(uint4*)(dst + j * 8) = make_uint4(u[4*j], u[4*j+1], u[4*j+2], u[4*j+3]);
        }
    }
}

// ---------------------------------------------------------------------------
// scores: g_Sh[b][q][k] = fp16( QK/32 + beta*ssm )
// ---------------------------------------------------------------------------
__global__ void __launch_bounds__(256) scores_k(
    const float* __restrict__ ssm, const float* __restrict__ beta_p)
{
    extern __shared__ char dsm[];
    const int t = threadIdx.x;
    const int lane = t & 31, wm = (t >> 5) & 3, wn = t >> 7;
    const uint32_t sm0 = su32(dsm);
    const int bz = blockIdx.z;
    const int m0 = blockIdx.y * 128, n0 = blockIdx.x * 128;

    float acc[2][8][4];
    ACC_INIT(acc)

    const char* Ab = (const char*)(g_Qh + ((size_t)bz * SDIM + m0) * HDIM);
    const char* Bb = (const char*)(g_Kh + ((size_t)bz * SDIM + n0) * HDIM);
    hmma_nt(Ab, (size_t)HDIM * 2, Bb, (size_t)HDIM * 2, HDIM / 32, sm0, t, acc);

    const float beta = beta_p[0];
    const float inv = 1.0f / 32.0f;
    const int g = lane >> 2, qd = lane & 3;
#pragma unroll
    for (int mi = 0; mi < 2; mi++)
#pragma unroll
        for (int h2 = 0; h2 < 2; h2++) {
            const int m = m0 + wm * 32 + mi * 16 + g + h2 * 8;
            const float* srow = ssm + ((size_t)bz * SDIM + m) * SDIM + n0;
            __half* drow = g_Sh + ((size_t)bz * SDIM + m) * SDIM + n0;
#pragma unroll
            for (int ni = 0; ni < 8; ni++) {
                const int col = wn * 64 + ni * 8 + qd * 2;
                const float2 s2 = *(const float2*)(srow + col);
                const float v0 = acc[mi][ni][h2 * 2 + 0] * inv + beta * s2.x;
                const float v1 = acc[mi][ni][h2 * 2 + 1] * inv + beta * s2.y;
                *(__half2*)(drow + col) = __floats2half2_rn(v0, v1);
            }
        }
}

// ---------------------------------------------------------------------------
// softmax: in-place on g_Sh rows (fp16 storage, fp32 math). 1 CTA / row.
// ---------------------------------------------------------------------------
__global__ void __launch_bounds__(256) softmax_k()
{
    __shared__ float redm[8], reds[8], bcast[2];
    const int row = blockIdx.x;
    __half* p = g_Sh + (size_t)row * SDIM;
    const int t = threadIdx.x, lane = t & 31, warp = t >> 5;

    uint4 raw = ((const uint4*)p)[t];
    __half2 h[4] = { *(__half2*)&raw.x, *(__half2*)&raw.y,
                     *(__half2*)&raw.z, *(__half2*)&raw.w };
    float v[8];
#pragma unroll
    for (int i = 0; i < 4; i++) {
        float2 f = __half22float2(h[i]);
        v[2 * i] = f.x; v[2 * i + 1] = f.y;
    }
    float m = -3.0e38f;
#pragma unroll
    for (int i = 0; i < 8; i++) m = fmaxf(m, v[i]);
#pragma unroll
    for (int o = 16; o; o >>= 1) m = fmaxf(m, __shfl_xor_sync(0xffffffffu, m, o));
    if (lane == 0) redm[warp] = m;
    __syncthreads();
    if (t == 0) {
        float mm = redm[0];
#pragma unroll
        for (int w = 1; w < 8; w++) mm = fmaxf(mm, redm[w]);
        bcast[0] = mm;
    }
    __syncthreads();
    m = bcast[0];

    float ssum = 0.0f;
#pragma unroll
    for (int i = 0; i < 8; i++) { v[i] = __expf(v[i] - m); ssum += v[i]; }
#pragma unroll
    for (int o = 16; o; o >>= 1) ssum += __shfl_xor_sync(0xffffffffu, ssum, o);
    if (lane == 0) reds[warp] = ssum;
    __syncthreads();
    if (t == 0) {
        float s = reds[0];
#pragma unroll
        for (int w = 1; w < 8; w++) s += reds[w];
        bcast[1] = 1.0f / s;
    }
    __syncthreads();
    const float inv = bcast[1];
    uint4 outw;
    outw.x = h2bits(__floats2half2_rn(v[0] * inv, v[1] * inv));
    outw.y = h2bits(__floats2half2_rn(v[2] * inv, v[3] * inv));
    outw.z = h2bits(__floats2half2_rn(v[4] * inv, v[5] * inv));
    outw.w = h2bits(__floats2half2_rn(v[6] * inv, v[7] * inv));
    ((uint4*)p)[t] = outw;
}

// ---------------------------------------------------------------------------
// av: out[q][b][h] = sum_k attn[b][q][k] * VT[b][h][k]   (fp32 out)
// ---------------------------------------------------------------------------
__global__ void __launch_bounds__(256) av_k(float* __restrict__ out)
{
    extern __shared__ char dsm[];
    const int t = threadIdx.x;
    const int lane = t & 31, wm = (t >> 5) & 3, wn = t >> 7;
    const uint32_t sm0 = su32(dsm);
    const int bz = blockIdx.z;
    const int m0 = blockIdx.y * 128, n0 = blockIdx.x * 128;

    float acc[2][8][4];
    ACC_INIT(acc)

    const char* Ab = (const char*)(g_Sh + ((size_t)bz * SDIM + m0) * SDIM);
    const char* Bb = (const char*)(g_VT + ((size_t)bz * HDIM + n0) * SDIM);
    hmma_nt(Ab, (size_t)SDIM * 2, Bb, (size_t)SDIM * 2, SDIM / 32, sm0, t, acc);

    const int g = lane >> 2, qd = lane & 3;
#pragma unroll
    for (int mi = 0; mi < 2; mi++)
#pragma unroll
        for (int h2 = 0; h2 < 2; h2++) {
            const int m = m0 + wm * 32 + mi * 16 + g + h2 * 8;
            float* orow = out + ((size_t)m * BDIM + bz) * HDIM + n0;
#pragma unroll
            for (int ni = 0; ni < 8; ni++) {
                const int col = wn * 64 + ni * 8 + qd * 2;
                *(float2*)(orow + col) =
                    make_float2(acc[mi][ni][h2 * 2 + 0], acc[mi][ni][h2 * 2 + 1]);
            }
        }
}

// ---------------------------------------------------------------------------
extern "C" void kernel_launch(void* const* d_in, const int* in_sizes, int n_in,
                              void* d_out, int out_size)
{
    const float* x    = (const float*)d_in[0];
    const float* ssm  = (const float*)d_in[1];
    const float* Wq   = (const float*)d_in[2];
    const float* bq   = (const float*)d_in[3];
    const float* Wk   = (const float*)d_in[4];
    const float* bk   = (const float*)d_in[5];
    const float* Wv   = (const float*)d_in[6];
    const float* bv   = (const float*)d_in[7];
    const float* beta = (const float*)d_in[8];
    float* out = (float*)d_out;

    dim3 blk(256);
    proj_k<<<dim3(HDIM / 128, (SDIM * BDIM) / 128, 3), blk, SMEMB>>>(
        x, Wq, bq, Wk, bk, Wv, bv);
    scores_k<<<dim3(SDIM / 128, SDIM / 128, BDIM), blk, SMEMB>>>(ssm, beta);
    softmax_k<<<dim3(BDIM * SDIM), blk>>>();
    av_k<<<dim3(HDIM / 128, SDIM / 128, BDIM), blk, SMEMB>>>(out);
}

// round 9
// speedup vs baseline: 6.4659x; 1.2227x over previous
#include <cuda_runtime.h>
#include <cuda_fp16.h>
#include <cstdint>

#define SDIM 2048
#define BDIM 4
#define HDIM 1024

// fp16 scratch (device globals: allocation-free, graph-capturable)
__device__ __half g_X16[(size_t)SDIM * BDIM * HDIM];      // [s*B+b][h] 16 MB
__device__ __half g_W16[3][(size_t)HDIM * HDIM];          // Wq/Wk/Wv fp16 6 MB
__device__ __half g_Qh[(size_t)BDIM * SDIM * HDIM];       // [b][s][h] 16 MB
__device__ __half g_Kh[(size_t)BDIM * SDIM * HDIM];       // [b][s][h] 16 MB
__device__ __half g_VT[(size_t)BDIM * HDIM * SDIM];       // [b][h][s] 16 MB
__device__ __half g_Sh[(size_t)BDIM * SDIM * SDIM];       // [b][q][k] 32 MB

// ---------------------------------------------------------------------------
// helpers (base PTX only: family-portable on compute_103)
// ---------------------------------------------------------------------------
static __device__ __forceinline__ uint32_t su32(const void* p) {
    uint32_t a;
    asm("{ .reg .u64 t; cvta.to.shared.u64 t, %1; cvt.u32.u64 %0, t; }" : "=r"(a) : "l"(p));
    return a;
}
static __device__ __forceinline__ void cp16(uint32_t dst, const void* src) {
    asm volatile("cp.async.cg.shared.global [%0], [%1], 16;" :: "r"(dst), "l"(src));
}
static __device__ __forceinline__ void cp_commit() {
    asm volatile("cp.async.commit_group;" ::: "memory");
}
template <int N>
static __device__ __forceinline__ void cp_wait() {
    asm volatile("cp.async.wait_group %0;" :: "n"(N) : "memory");
}
static __device__ __forceinline__ void ldm_x4(uint32_t* r, uint32_t addr) {
    asm volatile("ldmatrix.sync.aligned.m8n8.x4.shared.b16 {%0,%1,%2,%3}, [%4];"
                 : "=r"(r[0]), "=r"(r[1]), "=r"(r[2]), "=r"(r[3]) : "r"(addr));
}
static __device__ __forceinline__ void mma16816(float* c, const uint32_t* a,
                                                uint32_t b0, uint32_t b1) {
    asm volatile(
        "mma.sync.aligned.m16n8k16.row.col.f32.f16.f16.f32 "
        "{%0,%1,%2,%3}, {%4,%5,%6,%7}, {%8,%9}, {%0,%1,%2,%3};"
        : "+f"(c[0]), "+f"(c[1]), "+f"(c[2]), "+f"(c[3])
        : "r"(a[0]), "r"(a[1]), "r"(a[2]), "r"(a[3]), "r"(b0), "r"(b1));
}
static __device__ __forceinline__ uint32_t h2bits(__half2 h) {
    return *reinterpret_cast<uint32_t*>(&h);
}

// ---------------------------------------------------------------------------
// Smem tile: 128 rows x 32 halves (64B), padded to 80B/row (conflict-free
// ldmatrix: 80B stride -> 8 rows hit 8 distinct 16B columns mod 128B).
// Stage: A @ +0 (10240B), B @ +10240. 4 stages, ring.
// ---------------------------------------------------------------------------
#define ROWB   80
#define STAGE  20480
#define NSTG   4
#define SMEMB  (NSTG * STAGE)      // 81920

static __device__ __forceinline__ void compute_chunk(
    uint32_t sbase, int lane, int wm, int wn, float acc[2][8][4])
{
#pragma unroll
    for (int kk = 0; kk < 2; kk++) {
        uint32_t a[2][4];
#pragma unroll
        for (int mi = 0; mi < 2; mi++) {
            uint32_t addr = sbase
                + (uint32_t)(wm * 32 + mi * 16 + (lane & 15)) * ROWB
                + kk * 32 + ((lane >> 4) << 4);
            ldm_x4(a[mi], addr);
        }
        uint32_t b[4][4];
#pragma unroll
        for (int ni2 = 0; ni2 < 4; ni2++) {
            uint32_t addr = sbase + 10240u
                + (uint32_t)(wn * 64 + ni2 * 16 + (lane & 7) + ((lane >> 4) << 3)) * ROWB
                + kk * 32 + (((lane >> 3) & 1) << 4);
            ldm_x4(b[ni2], addr);
        }
#pragma unroll
        for (int mi = 0; mi < 2; mi++)
#pragma unroll
            for (int ni = 0; ni < 8; ni++)
                mma16816(acc[mi][ni], a[mi],
                         b[ni >> 1][(ni & 1) * 2], b[ni >> 1][(ni & 1) * 2 + 1]);
    }
}

static __device__ __forceinline__ void cpa_issue(
    uint32_t sm, const char* Ag, size_t ldA, const char* Bg, size_t ldB,
    size_t kbyte, int t)
{
    const int row = t >> 1;
    const int c = (t & 1) * 32;
    uint32_t da = sm + (uint32_t)row * ROWB + c;
    const char* sa = Ag + (size_t)row * ldA + kbyte + c;
    cp16(da, sa); cp16(da + 16, sa + 16);
    uint32_t db = sm + 10240u + (uint32_t)row * ROWB + c;
    const char* sb = Bg + (size_t)row * ldB + kbyte + c;
    cp16(db, sb); cp16(db + 16, sb + 16);
}

// 4-stage cp.async ring, ONE __syncthreads per chunk.
// At iter i: wait chunk i, barrier, issue chunk i+3 into stage (i+3)&3
// (== (i-1)&3, fully consumed before this barrier), then compute chunk i.
static __device__ __forceinline__ void hmma_nt(
    const char* Ag, size_t ldA, const char* Bg, size_t ldB, int nch,
    uint32_t sm0, int t, float acc[2][8][4])
{
    const int lane = t & 31, wm = (t >> 5) & 3, wn = t >> 7;
#pragma unroll
    for (int p = 0; p < 3; p++) {
        cpa_issue(sm0 + p * STAGE, Ag, ldA, Bg, ldB, (size_t)p * 64, t);
        cp_commit();
    }
    for (int i = 0; i < nch; i++) {
        if (i < nch - 2)       cp_wait<2>();
        else if (i == nch - 2) cp_wait<1>();
        else                   cp_wait<0>();
        __syncthreads();
        if (i + 3 < nch) {
            cpa_issue(sm0 + ((i + 3) & 3) * STAGE, Ag, ldA, Bg, ldB,
                      (size_t)(i + 3) * 64, t);
            cp_commit();
        }
        compute_chunk(sm0 + (i & 3) * STAGE, lane, wm, wn, acc);
    }
}

#define ACC_INIT(acc)                                                          \
    _Pragma("unroll")                                                          \
    for (int i_ = 0; i_ < 2; i_++)                                             \
        _Pragma("unroll")                                                      \
        for (int j_ = 0; j_ < 8; j_++)                                         \
            _Pragma("unroll")                                                  \
            for (int k_ = 0; k_ < 4; k_++) (acc)[i_][j_][k_] = 0.0f;

// ---------------------------------------------------------------------------
// cvt: fp32 -> fp16 elementwise (x and the three W matrices)
// ---------------------------------------------------------------------------
__global__ void __launch_bounds__(256) cvt_k(
    const float4* __restrict__ src, uint2* __restrict__ dst, int n4)
{
    const int i = blockIdx.x * 256 + threadIdx.x;
    if (i < n4) {
        const float4 f = src[i];
        dst[i] = make_uint2(h2bits(__floats2half2_rn(f.x, f.y)),
                            h2bits(__floats2half2_rn(f.z, f.w)));
    }
}

// ---------------------------------------------------------------------------
// proj: C[m][n] = sum_h x[m][h]*W[n][h] + bias[n]; fp16 NT GEMM.
// z=0 -> g_Qh, z=1 -> g_Kh, z=2 -> V transposed into g_VT[b][h][s].
// ---------------------------------------------------------------------------
__global__ void __launch_bounds__(256) proj_k(
    const float* __restrict__ bq, const float* __restrict__ bk,
    const float* __restrict__ bv)
{
    extern __shared__ char dsm[];
    const int t = threadIdx.x;
    const int lane = t & 31, wm = (t >> 5) & 3, wn = t >> 7;
    const uint32_t sm0 = su32(dsm);
    const int z = blockIdx.z;
    const float* bias = (z == 0) ? bq : (z == 1) ? bk : bv;
    const int m0 = blockIdx.y * 128, n0 = blockIdx.x * 128;
    const char* Ab = (const char*)(g_X16 + (size_t)m0 * HDIM);
    const char* Bb = (const char*)(g_W16[z] + (size_t)n0 * HDIM);

    float acc[2][8][4];
    ACC_INIT(acc)
    hmma_nt(Ab, (size_t)HDIM * 2, Bb, (size_t)HDIM * 2, HDIM / 32, sm0, t, acc);

    const int g = lane >> 2, qd = lane & 3;
    if (z < 2) {
        __half* out = z ? g_Kh : g_Qh;
#pragma unroll
        for (int mi = 0; mi < 2; mi++)
#pragma unroll
            for (int h2 = 0; h2 < 2; h2++) {
                const int m = m0 + wm * 32 + mi * 16 + g + h2 * 8;
                const int s = m >> 2, b = m & 3;
                __half* orow = out + ((size_t)b * SDIM + s) * HDIM + n0;
#pragma unroll
                for (int ni = 0; ni < 8; ni++) {
                    const int col = wn * 64 + ni * 8 + qd * 2;
                    const float v0 = acc[mi][ni][h2 * 2 + 0] + bias[n0 + col];
                    const float v1 = acc[mi][ni][h2 * 2 + 1] + bias[n0 + col + 1];
                    *(__half2*)(orow + col) = __floats2half2_rn(v0, v1);
                }
            }
    } else {
        __syncthreads();
        __half* Tr = (__half*)dsm;     // 128 x 128, stride 132 halves (33.8KB)
#pragma unroll
        for (int mi = 0; mi < 2; mi++)
#pragma unroll
            for (int h2 = 0; h2 < 2; h2++) {
                const int ml = wm * 32 + mi * 16 + g + h2 * 8;
#pragma unroll
                for (int ni = 0; ni < 8; ni++) {
                    const int col = wn * 64 + ni * 8 + qd * 2;
                    const float v0 = acc[mi][ni][h2 * 2 + 0] + bias[n0 + col];
                    const float v1 = acc[mi][ni][h2 * 2 + 1] + bias[n0 + col + 1];
                    *(__half2*)(Tr + (size_t)ml * 132 + col) = __floats2half2_rn(v0, v1);
                }
            }
        __syncthreads();
        const int s0 = blockIdx.y * 32;
#pragma unroll 1
        for (int rr = t; rr < 512; rr += 256) {
            const int h = rr >> 2, b = rr & 3;
            __half* dst = g_VT + ((size_t)b * HDIM + n0 + h) * SDIM + s0;
            uint32_t u[16];
#pragma unroll
            for (int s = 0; s < 32; s += 2) {
                u[s >> 1] = h2bits(__halves2half2(
                    Tr[(size_t)(s * 4 + b) * 132 + h],
                    Tr[(size_t)((s + 1) * 4 + b) * 132 + h]));
            }
#pragma unroll
            for (int j = 0; j < 4; j++)
                *(uint4*)(dst + j * 8) = make_uint4(u[4*j], u[4*j+1], u[4*j+2], u[4*j+3]);
        }
    }
}

// ---------------------------------------------------------------------------
// scores: g_Sh[b][q][k] = fp16( QK/32 + beta*ssm )
// ---------------------------------------------------------------------------
__global__ void __launch_bounds__(256) scores_k(
    const float* __restrict__ ssm, const float* __restrict__ beta_p)
{
    extern __shared__ char dsm[];
    const int t = threadIdx.x;
    const int lane = t & 31, wm = (t >> 5) & 3, wn = t >> 7;
    const uint32_t sm0 = su32(dsm);
    const int bz = blockIdx.z;
    const int m0 = blockIdx.y * 128, n0 = blockIdx.x * 128;

    float acc[2][8][4];
    ACC_INIT(acc)

    const char* Ab = (const char*)(g_Qh + ((size_t)bz * SDIM + m0) * HDIM);
    const char* Bb = (const char*)(g_Kh + ((size_t)bz * SDIM + n0) * HDIM);
    hmma_nt(Ab, (size_t)HDIM * 2, Bb, (size_t)HDIM * 2, HDIM / 32, sm0, t, acc);

    const float beta = beta_p[0];
    const float inv = 1.0f / 32.0f;
    const int g = lane >> 2, qd = lane & 3;
#pragma unroll
    for (int mi = 0; mi < 2; mi++)
#pragma unroll
        for (int h2 = 0; h2 < 2; h2++) {
            const int m = m0 + wm * 32 + mi * 16 + g + h2 * 8;
            const float* srow = ssm + ((size_t)bz * SDIM + m) * SDIM + n0;
            __half* drow = g_Sh + ((size_t)bz * SDIM + m) * SDIM + n0;
#pragma unroll
            for (int ni = 0; ni < 8; ni++) {
                const int col = wn * 64 + ni * 8 + qd * 2;
                const float2 s2 = *(const float2*)(srow + col);
                const float v0 = acc[mi][ni][h2 * 2 + 0] * inv + beta * s2.x;
                const float v1 = acc[mi][ni][h2 * 2 + 1] * inv + beta * s2.y;
                *(__half2*)(drow + col) = __floats2half2_rn(v0, v1);
            }
        }
}

// ---------------------------------------------------------------------------
// softmax: in-place on g_Sh rows (fp16 storage, fp32 math). 1 CTA / row.
// ---------------------------------------------------------------------------
__global__ void __launch_bounds__(256) softmax_k()
{
    __shared__ float redm[8], reds[8], bcast[2];
    const int row = blockIdx.x;
    __half* p = g_Sh + (size_t)row * SDIM;
    const int t = threadIdx.x, lane = t & 31, warp = t >> 5;

    uint4 raw = ((const uint4*)p)[t];
    __half2 h[4] = { *(__half2*)&raw.x, *(__half2*)&raw.y,
                     *(__half2*)&raw.z, *(__half2*)&raw.w };
    float v[8];
#pragma unroll
    for (int i = 0; i < 4; i++) {
        float2 f = __half22float2(h[i]);
        v[2 * i] = f.x; v[2 * i + 1] = f.y;
    }
    float m = -3.0e38f;
#pragma unroll
    for (int i = 0; i < 8; i++) m = fmaxf(m, v[i]);
#pragma unroll
    for (int o = 16; o; o >>= 1) m = fmaxf(m, __shfl_xor_sync(0xffffffffu, m, o));
    if (lane == 0) redm[warp] = m;
    __syncthreads();
    if (t == 0) {
        float mm = redm[0];
#pragma unroll
        for (int w = 1; w < 8; w++) mm = fmaxf(mm, redm[w]);
        bcast[0] = mm;
    }
    __syncthreads();
    m = bcast[0];

    float ssum = 0.0f;
#pragma unroll
    for (int i = 0; i < 8; i++) { v[i] = __expf(v[i] - m); ssum += v[i]; }
#pragma unroll
    for (int o = 16; o; o >>= 1) ssum += __shfl_xor_sync(0xffffffffu, ssum, o);
    if (lane == 0) reds[warp] = ssum;
    __syncthreads();
    if (t == 0) {
        float s = reds[0];
#pragma unroll
        for (int w = 1; w < 8; w++) s += reds[w];
        bcast[1] = 1.0f / s;
    }
    __syncthreads();
    const float inv = bcast[1];
    uint4 outw;
    outw.x = h2bits(__floats2half2_rn(v[0] * inv, v[1] * inv));
    outw.y = h2bits(__floats2half2_rn(v[2] * inv, v[3] * inv));
    outw.z = h2bits(__floats2half2_rn(v[4] * inv, v[5] * inv));
    outw.w = h2bits(__floats2half2_rn(v[6] * inv, v[7] * inv));
    ((uint4*)p)[t] = outw;
}

// ---------------------------------------------------------------------------
// av: out[q][b][h] = sum_k attn[b][q][k] * VT[b][h][k]   (fp32 out)
// ---------------------------------------------------------------------------
__global__ void __launch_bounds__(256) av_k(float* __restrict__ out)
{
    extern __shared__ char dsm[];
    const int t = threadIdx.x;
    const int lane = t & 31, wm = (t >> 5) & 3, wn = t >> 7;
    const uint32_t sm0 = su32(dsm);
    const int bz = blockIdx.z;
    const int m0 = blockIdx.y * 128, n0 = blockIdx.x * 128;

    float acc[2][8][4];
    ACC_INIT(acc)

    const char* Ab = (const char*)(g_Sh + ((size_t)bz * SDIM + m0) * SDIM);
    const char* Bb = (const char*)(g_VT + ((size_t)bz * HDIM + n0) * SDIM);
    hmma_nt(Ab, (size_t)SDIM * 2, Bb, (size_t)SDIM * 2, SDIM / 32, sm0, t, acc);

    const int g = lane >> 2, qd = lane & 3;
#pragma unroll
    for (int mi = 0; mi < 2; mi++)
#pragma unroll
        for (int h2 = 0; h2 < 2; h2++) {
            const int m = m0 + wm * 32 + mi * 16 + g + h2 * 8;
            float* orow = out + ((size_t)m * BDIM + bz) * HDIM + n0;
#pragma unroll
            for (int ni = 0; ni < 8; ni++) {
                const int col = wn * 64 + ni * 8 + qd * 2;
                *(float2*)(orow + col) =
                    make_float2(acc[mi][ni][h2 * 2 + 0], acc[mi][ni][h2 * 2 + 1]);
            }
        }
}

// ---------------------------------------------------------------------------
extern "C" void kernel_launch(void* const* d_in, const int* in_sizes, int n_in,
                              void* d_out, int out_size)
{
    const float* x    = (const float*)d_in[0];
    const float* ssm  = (const float*)d_in[1];
    const float* Wq   = (const float*)d_in[2];
    const float* bq   = (const float*)d_in[3];
    const float* Wk   = (const float*)d_in[4];
    const float* bk   = (const float*)d_in[5];
    const float* Wv   = (const float*)d_in[6];
    const float* bv   = (const float*)d_in[7];
    const float* beta = (const float*)d_in[8];
    float* out = (float*)d_out;

    static int attr_done = 0;
    if (!attr_done) {
        cudaFuncSetAttribute(proj_k,   cudaFuncAttributeMaxDynamicSharedMemorySize, SMEMB);
        cudaFuncSetAttribute(scores_k, cudaFuncAttributeMaxDynamicSharedMemorySize, SMEMB);
        cudaFuncSetAttribute(av_k,     cudaFuncAttributeMaxDynamicSharedMemorySize, SMEMB);
        attr_done = 1;
    }

    // resolve device-global addresses host-side for cvt kernels
    __half* x16; __half* w16;
    cudaGetSymbolAddress((void**)&x16, g_X16);
    cudaGetSymbolAddress((void**)&w16, g_W16);

    dim3 blk(256);
    const int n4x = SDIM * BDIM * HDIM / 4;     // 2097152
    const int n4w = HDIM * HDIM / 4;            // 262144
    cvt_k<<<n4x / 256, blk>>>((const float4*)x, (uint2*)x16, n4x);
    cvt_k<<<n4w / 256, blk>>>((const float4*)Wq, (uint2*)(w16 + 0 * (size_t)HDIM * HDIM), n4w);
    cvt_k<<<n4w / 256, blk>>>((const float4*)Wk, (uint2*)(w16 + 1 * (size_t)HDIM * HDIM), n4w);
    cvt_k<<<n4w / 256, blk>>>((const float4*)Wv, (uint2*)(w16 + 2 * (size_t)HDIM * HDIM), n4w);

    proj_k<<<dim3(HDIM / 128, (SDIM * BDIM) / 128, 3), blk, SMEMB>>>(bq, bk, bv);
    scores_k<<<dim3(SDIM / 128, SDIM / 128, BDIM), blk, SMEMB>>>(ssm, beta);
    softmax_k<<<dim3(BDIM * SDIM), blk>>>();
    av_k<<<dim3(HDIM / 128, SDIM / 128, BDIM), blk, SMEMB>>>(out);
}